// round 6
// baseline (speedup 1.0000x reference)
#include <cuda_runtime.h>
#include <cuda_bf16.h>
#include <cstdint>

// ExponentialSmoothingLayer: s_0 = x_0; s_t = a*x_t + (1-a)*s_{t-1}, a = sigmoid(alpha[d])
// x: (B=16, T=4096, D=512) fp32 -> out same shape.
//
// v3: PERSISTENT double-buffered single-pass decoupled-lookback scan.
//  - 444 persistent blocks (3/SM), ticket loop; tile = (b, 16 t, 512 d) = 32 KB
//  - two-deep smem ring: TMA load of ticket i+1 issued before processing ticket i
//    -> load of next tile overlaps scan+lookback+store of current (continuous DRAM)
//  - window lookback (32 statuses, one coalesced read + ballot), Q^i truncation
//  - sigmoid/Q computed once per block (persistent reuse)

#define B_  16
#define T_  4096
#define D_  512
#define L_  16
#define NTB (T_ / L_)            // 256 tiles per batch row
#define NTILES (B_ * NTB)        // 4096
#define TPB 512
#define TILE_BYTES (L_ * D_ * 4) // 32768
#define GRID 444                 // 148 SMs * 3 blocks

// -------- scratch (static device arrays; no runtime allocation) --------
__device__ float        g_agg [NTILES * D_];   // per-tile local-scan last value
__device__ float        g_incl[NTILES * D_];   // per-tile true inclusive state
__device__ int          g_status[NTILES];      // [b][tb]: 0 / 1(agg) / 2(incl)
__device__ unsigned int g_ticket;

// -------- PTX helpers --------
__device__ __forceinline__ int ld_acquire(const int* p) {
    int v; asm volatile("ld.acquire.gpu.s32 %0, [%1];" : "=r"(v) : "l"(p) : "memory"); return v;
}
__device__ __forceinline__ void st_release(int* p, int v) {
    asm volatile("st.release.gpu.s32 [%0], %1;" :: "l"(p), "r"(v) : "memory");
}
__device__ __forceinline__ unsigned smem_u32(const void* p) {
    unsigned a;
    asm("{ .reg .u64 t; cvta.to.shared.u64 t, %1; cvt.u32.u64 %0, t; }" : "=r"(a) : "l"(p));
    return a;
}
__device__ __forceinline__ void mbar_wait(unsigned mb, unsigned parity) {
    unsigned done;
    asm volatile(
        "{\n\t.reg .pred p;\n\t"
        "mbarrier.try_wait.parity.acquire.cta.shared::cta.b64 p, [%1], %2;\n\t"
        "selp.b32 %0, 1, 0, p;\n\t}"
        : "=r"(done) : "r"(mb), "r"(parity) : "memory");
    while (!done) {
        asm volatile(
            "{\n\t.reg .pred p;\n\t"
            "mbarrier.try_wait.parity.acquire.cta.shared::cta.b64 p, [%1], %2, 0x989680;\n\t"
            "selp.b32 %0, 1, 0, p;\n\t}"
            : "=r"(done) : "r"(mb), "r"(parity) : "memory");
    }
}

// -------- per-replay flag reset --------
__global__ void es_clear_kernel() {
    int i = blockIdx.x * blockDim.x + threadIdx.x;
    if (i < NTILES) g_status[i] = 0;
    if (i == 0)     g_ticket = 0u;
}

__global__ void __launch_bounds__(TPB, 3)
es_scan_kernel(const float* __restrict__ x,
               const float* __restrict__ alpha,
               float* __restrict__ out) {
    extern __shared__ float buf[];                  // 2 * L_ * D_ floats (64 KB ring)
    __shared__ unsigned long long mbar[2];
    __shared__ unsigned s_tk;                       // broadcast: ticket for NEXT iter
    __shared__ int s_w;

    const int tid = threadIdx.x;

    if (tid == 0) {
        asm volatile("mbarrier.init.shared.b64 [%0], 1;" :: "r"(smem_u32(&mbar[0])) : "memory");
        asm volatile("mbarrier.init.shared.b64 [%0], 1;" :: "r"(smem_u32(&mbar[1])) : "memory");
        s_tk = atomicAdd(&g_ticket, 1u);
    }
    __syncthreads();

    // per-channel coefficients, computed once per persistent block
    const float av = alpha[tid];
    const float a  = 1.0f / (1.0f + __expf(-av));
    const float q  = 1.0f - a;
    float Q = q;                                     // Q = q^16
    #pragma unroll
    for (int i = 0; i < 4; ++i) Q *= Q;

    unsigned tk = s_tk;
    int cur = 0;
    unsigned phase[2] = {0u, 0u};

    // issue TMA for the first ticket
    if (tk < NTILES && tid == 0) {
        const int b0 = (int)(tk & (B_ - 1)), tb0 = (int)(tk >> 4);
        const size_t base0 = ((size_t)b0 * T_ + (size_t)tb0 * L_) * (size_t)D_;
        unsigned mb = smem_u32(&mbar[0]);
        asm volatile("mbarrier.arrive.expect_tx.shared.b64 _, [%0], %1;"
                     :: "r"(mb), "r"((unsigned)TILE_BYTES) : "memory");
        asm volatile("cp.async.bulk.shared::cta.global.mbarrier::complete_tx::bytes "
                     "[%0], [%1], %2, [%3];"
                     :: "r"(smem_u32(buf)), "l"(x + base0),
                        "r"((unsigned)TILE_BYTES), "r"(mb) : "memory");
    }

    while (tk < NTILES) {
        const int nxt = cur ^ 1;

        // grab + prefetch the NEXT ticket into the other buffer (overlaps everything below)
        if (tid == 0) {
            unsigned nt = atomicAdd(&g_ticket, 1u);
            s_tk = nt;
            if (nt < NTILES) {
                const int bn = (int)(nt & (B_ - 1)), tbn = (int)(nt >> 4);
                const size_t basen = ((size_t)bn * T_ + (size_t)tbn * L_) * (size_t)D_;
                unsigned mb = smem_u32(&mbar[nxt]);
                asm volatile("mbarrier.arrive.expect_tx.shared.b64 _, [%0], %1;"
                             :: "r"(mb), "r"((unsigned)TILE_BYTES) : "memory");
                asm volatile("cp.async.bulk.shared::cta.global.mbarrier::complete_tx::bytes "
                             "[%0], [%1], %2, [%3];"
                             :: "r"(smem_u32(buf + (size_t)nxt * (L_ * D_))), "l"(x + basen),
                                "r"((unsigned)TILE_BYTES), "r"(mb) : "memory");
            }
        }

        const int b  = (int)(tk & (B_ - 1));
        const int tb = (int)(tk >> 4);
        const int lin = b * NTB + tb;
        const size_t base = ((size_t)b * T_ + (size_t)tb * L_) * (size_t)D_;
        float* tile = buf + (size_t)cur * (L_ * D_);

        // wait for current tile's data
        mbar_wait(smem_u32(&mbar[cur]), phase[cur]);
        phase[cur] ^= 1u;

        // pass 1: local scan with zero incoming state, write locals back to smem
        float s = 0.0f, x0;
        #pragma unroll
        for (int t = 0; t < L_; ++t) {
            float v = tile[t * D_ + tid];
            if (t == 0) x0 = v;
            s = fmaf(q, s, a * v);
            tile[t * D_ + tid] = s;
        }
        const float last = s;

        // ---- resolve incoming state carry = inclusive of predecessor tile ----
        float carry;
        if (tb == 0) {
            carry = x0;                              // s_0 = x_0  <=>  S_in = x_0
        } else {
            // publish aggregate first (wait-free forward progress)
            g_agg[(size_t)lin * D_ + tid] = last;
            __threadfence();
            __syncthreads();
            if (tid == 0) st_release(&g_status[lin], 1);

            // parallel-window lookback: warp 0 scans 32 statuses at once
            if (tid < 32) {
                const int idx = tb - 1 - tid;
                const int* sp = &g_status[b * NTB + idx];
                for (;;) {
                    int st = (idx >= 0) ? ld_acquire(sp) : 0;
                    unsigned m2 = __ballot_sync(0xffffffffu, st == 2);
                    unsigned m0 = __ballot_sync(0xffffffffu, st == 0);
                    if (m2) {
                        int i2 = __ffs(m2) - 1;                   // nearest INCLUSIVE
                        if ((m0 & ((1u << i2) - 1u)) == 0u) {     // all nearer have agg
                            if (tid == 0) s_w = i2;
                            break;
                        }
                    }
                    __nanosleep(60);
                }
            }
            __syncthreads();
            const int i2 = s_w;

            // carry = sum_{i<i2} Q^i * agg[tb-1-i]  +  Q^i2 * incl[tb-1-i2]
            // truncate: Q^i < 1e-12 contributes < 1e-12 (tol 1e-3)
            const size_t pbase = (size_t)(b * NTB + tb - 1) * D_ + tid;
            carry = 0.0f;
            float coef = 1.0f;
            for (int i = 0; i < i2; ++i) {
                if (coef > 1e-12f)
                    carry = fmaf(coef, g_agg[pbase - (size_t)i * D_], carry);
                coef *= Q;
            }
            if (coef > 1e-12f || i2 == 0)
                carry = fmaf(coef, g_incl[pbase - (size_t)i2 * D_], carry);
        }

        // publish inclusive: state at tile end = last + Q * S_in
        g_incl[(size_t)lin * D_ + tid] = fmaf(Q, carry, last);
        __threadfence();
        __syncthreads();
        if (tid == 0) st_release(&g_status[lin], 2);

        // pass 2: fixup + coalesced store: s_{t0+t} = local_t + q^{t+1} * S_in
        float* op = out + base + tid;
        float c = q;
        #pragma unroll
        for (int t = 0; t < L_; ++t) {
            op[(size_t)t * D_] = fmaf(c, carry, tile[t * D_ + tid]);
            c *= q;
        }

        // end-of-iteration barrier: protects buf[nxt] from next iteration's TMA
        // and makes s_tk (next ticket) visible to all threads
        __syncthreads();
        tk = s_tk;
        cur = nxt;
    }
}

extern "C" void kernel_launch(void* const* d_in, const int* in_sizes, int n_in,
                              void* d_out, int out_size) {
    const float* x     = (const float*)d_in[0];   // (16, 4096, 512) fp32
    const float* alpha = (const float*)d_in[1];   // (1, 1, 512) fp32
    float* out = (float*)d_out;
    (void)in_sizes; (void)n_in; (void)out_size;

    static bool attr_set = false;
    if (!attr_set) {
        cudaFuncSetAttribute(es_scan_kernel,
                             cudaFuncAttributeMaxDynamicSharedMemorySize,
                             2 * TILE_BYTES);
        attr_set = true;
    }

    es_clear_kernel<<<(NTILES + 255) / 256, 256>>>();
    es_scan_kernel<<<GRID, TPB, 2 * TILE_BYTES>>>(x, alpha, out);
}

// round 9
// speedup vs baseline: 1.4109x; 1.4109x over previous
#include <cuda_runtime.h>
#include <cuda_bf16.h>
#include <cstdint>

// ExponentialSmoothingLayer: s_0 = x_0; s_t = a*x_t + (1-a)*s_{t-1}, a = sigmoid(alpha[d])
// x: (B=16, T=4096, D=512) fp32 -> out same shape.
//
// v4: R3 structure (one 64KB tile per block, L=32, window lookback) PLUS
//     speculative EARLY lookback overlapped with the TMA wait:
//     warp 0 polls predecessor statuses and the TMA mbarrier together;
//     if the carry resolves before the data lands, the spin cost disappears.
//     Fallback path is exactly R3 (publish AGG, window lookback) -> strict superset.

#define B_  16
#define T_  4096
#define D_  512
#define L_  32
#define NTB (T_ / L_)            // 128 tiles per batch row
#define NTILES (B_ * NTB)        // 2048
#define TPB 512
#define TILE_BYTES (L_ * D_ * 4) // 65536

// -------- scratch (static device arrays; no runtime allocation) --------
__device__ float        g_agg [NTILES * D_];   // per-tile local-scan last value
__device__ float        g_incl[NTILES * D_];   // per-tile true inclusive state
__device__ int          g_status[NTILES];      // [b][tb]: 0 / 1(agg) / 2(incl)
__device__ unsigned int g_ticket;

// -------- PTX helpers --------
__device__ __forceinline__ int ld_acquire(const int* p) {
    int v; asm volatile("ld.acquire.gpu.s32 %0, [%1];" : "=r"(v) : "l"(p) : "memory"); return v;
}
__device__ __forceinline__ void st_release(int* p, int v) {
    asm volatile("st.release.gpu.s32 [%0], %1;" :: "l"(p), "r"(v) : "memory");
}
__device__ __forceinline__ unsigned smem_u32(const void* p) {
    unsigned a;
    asm("{ .reg .u64 t; cvta.to.shared.u64 t, %1; cvt.u32.u64 %0, t; }" : "=r"(a) : "l"(p));
    return a;
}
__device__ __forceinline__ int mbar_test(unsigned mb) {   // non-blocking, parity 0
    unsigned done;
    asm volatile(
        "{\n\t.reg .pred p;\n\t"
        "mbarrier.try_wait.parity.acquire.cta.shared::cta.b64 p, [%1], 0;\n\t"
        "selp.b32 %0, 1, 0, p;\n\t}"
        : "=r"(done) : "r"(mb) : "memory");
    return (int)done;
}
__device__ __forceinline__ void mbar_wait(unsigned mb) {  // blocking, parity 0
    unsigned done = 0;
    while (!done) {
        asm volatile(
            "{\n\t.reg .pred p;\n\t"
            "mbarrier.try_wait.parity.acquire.cta.shared::cta.b64 p, [%1], 0, 0x989680;\n\t"
            "selp.b32 %0, 1, 0, p;\n\t}"
            : "=r"(done) : "r"(mb) : "memory");
    }
}

// -------- per-replay flag reset --------
__global__ void es_clear_kernel() {
    int i = blockIdx.x * blockDim.x + threadIdx.x;
    if (i < NTILES) g_status[i] = 0;
    if (i == 0)     g_ticket = 0u;
}

__global__ void __launch_bounds__(TPB, 3)
es_scan_kernel(const float* __restrict__ x,
               const float* __restrict__ alpha,
               float* __restrict__ out) {
    extern __shared__ float tile[];                 // L_ * D_ floats (64 KB)
    __shared__ unsigned long long mbar;
    __shared__ unsigned s_ticket;
    __shared__ int s_w;
    __shared__ int s_mode;                          // 1 = carry resolved before TMA

    const int tid = threadIdx.x;

    if (tid == 0) {
        s_ticket = atomicAdd(&g_ticket, 1u);
        asm volatile("mbarrier.init.shared.b64 [%0], 1;"
                     :: "r"(smem_u32(&mbar)) : "memory");
    }
    __syncthreads();

    const unsigned ticket = s_ticket;               // execution-start ordered
    const int b   = (int)(ticket & (B_ - 1));       // round-robin rows
    const int tb  = (int)(ticket >> 4);
    const int lin = b * NTB + tb;
    const size_t base = ((size_t)b * T_ + (size_t)tb * L_) * (size_t)D_;

    // one bulk async copy: 64 KB contiguous gmem -> smem
    if (tid == 0) {
        unsigned mb = smem_u32(&mbar);
        asm volatile("mbarrier.arrive.expect_tx.shared.b64 _, [%0], %1;"
                     :: "r"(mb), "r"((unsigned)TILE_BYTES) : "memory");
        asm volatile("cp.async.bulk.shared::cta.global.mbarrier::complete_tx::bytes "
                     "[%0], [%1], %2, [%3];"
                     :: "r"(smem_u32(tile)), "l"(x + base),
                        "r"((unsigned)TILE_BYTES), "r"(mb) : "memory");
    }

    // per-channel coefficients (overlaps TMA)
    const float av = alpha[tid];
    const float a  = 1.0f / (1.0f + __expf(-av));
    const float q  = 1.0f - a;
    float Q = q;                                    // Q = q^32
    #pragma unroll
    for (int i = 0; i < 5; ++i) Q *= Q;

    float carry = 0.0f;
    int have_carry = 0;

    // ---- phase A: speculative lookback, overlapped with the TMA wait ----
    if (tb != 0) {
        if (tid < 32) {
            const int idx = tb - 1 - tid;           // this lane's predecessor
            const int* sp = &g_status[b * NTB + idx];
            const unsigned mb = smem_u32(&mbar);
            for (;;) {
                int st = (idx >= 0) ? ld_acquire(sp) : 0;
                unsigned m2 = __ballot_sync(0xffffffffu, st == 2);
                unsigned m0 = __ballot_sync(0xffffffffu, st == 0);
                int ok = 0, i2 = 0;
                if (m2) {
                    i2 = __ffs(m2) - 1;                          // nearest INCLUSIVE
                    ok = ((m0 & ((1u << i2) - 1u)) == 0u);       // all nearer >= AGG
                }
                int tma_done = 0;
                if (tid == 0) tma_done = mbar_test(mb);
                tma_done = __shfl_sync(0xffffffffu, tma_done, 0);
                if (ok)       { if (tid == 0) { s_mode = 1; s_w = i2; } break; }
                if (tma_done) { if (tid == 0) { s_mode = 0; }           break; }
                __nanosleep(40);
            }
        }
        __syncthreads();

        if (s_mode == 1) {
            // carry resolved early: combine now (loads overlap TMA tail)
            const int i2 = s_w;
            const size_t pbase = (size_t)(lin - 1) * D_ + tid;
            float coef = 1.0f;
            for (int i = 0; i < i2; ++i) {
                if (coef > 1e-12f)
                    carry = fmaf(coef, g_agg[pbase - (size_t)i * D_], carry);
                coef *= Q;
            }
            if (coef > 1e-12f || i2 == 0)
                carry = fmaf(coef, g_incl[pbase - (size_t)i2 * D_], carry);
            have_carry = 1;
        }
    }

    // ---- wait for tile data, local scan ----
    mbar_wait(smem_u32(&mbar));

    float s = 0.0f, x0;
    #pragma unroll
    for (int t = 0; t < L_; ++t) {
        float v = tile[t * D_ + tid];
        if (t == 0) x0 = v;
        s = fmaf(q, s, a * v);
        tile[t * D_ + tid] = s;
    }
    const float last = s;

    if (tb == 0) { carry = x0; have_carry = 1; }    // s_0 = x_0  <=>  S_in = x_0

    // ---- phase B (fallback = R3): publish AGG, window lookback ----
    if (!have_carry) {
        g_agg[(size_t)lin * D_ + tid] = last;
        __threadfence();
        __syncthreads();
        if (tid == 0) st_release(&g_status[lin], 1);

        if (tid < 32) {
            const int idx = tb - 1 - tid;
            const int* sp = &g_status[b * NTB + idx];
            for (;;) {
                int st = (idx >= 0) ? ld_acquire(sp) : 0;
                unsigned m2 = __ballot_sync(0xffffffffu, st == 2);
                unsigned m0 = __ballot_sync(0xffffffffu, st == 0);
                if (m2) {
                    int i2 = __ffs(m2) - 1;
                    if ((m0 & ((1u << i2) - 1u)) == 0u) {
                        if (tid == 0) s_w = i2;
                        break;
                    }
                }
                __nanosleep(40);
            }
        }
        __syncthreads();
        const int i2 = s_w;

        const size_t pbase = (size_t)(lin - 1) * D_ + tid;
        float coef = 1.0f;
        for (int i = 0; i < i2; ++i) {
            if (coef > 1e-12f)
                carry = fmaf(coef, g_agg[pbase - (size_t)i * D_], carry);
            coef *= Q;
        }
        if (coef > 1e-12f || i2 == 0)
            carry = fmaf(coef, g_incl[pbase - (size_t)i2 * D_], carry);
    }

    // ---- publish inclusive: state at tile end = last + Q * S_in ----
    g_incl[(size_t)lin * D_ + tid] = fmaf(Q, carry, last);
    __threadfence();
    __syncthreads();
    if (tid == 0) st_release(&g_status[lin], 2);

    // ---- fixup + coalesced store: s_{t0+t} = local_t + q^{t+1} * S_in ----
    float* op = out + base + tid;
    float c = q;
    #pragma unroll
    for (int t = 0; t < L_; ++t) {
        op[(size_t)t * D_] = fmaf(c, carry, tile[t * D_ + tid]);
        c *= q;
    }
}

extern "C" void kernel_launch(void* const* d_in, const int* in_sizes, int n_in,
                              void* d_out, int out_size) {
    const float* x     = (const float*)d_in[0];   // (16, 4096, 512) fp32
    const float* alpha = (const float*)d_in[1];   // (1, 1, 512) fp32
    float* out = (float*)d_out;
    (void)in_sizes; (void)n_in; (void)out_size;

    static bool attr_set = false;
    if (!attr_set) {
        cudaFuncSetAttribute(es_scan_kernel,
                             cudaFuncAttributeMaxDynamicSharedMemorySize,
                             TILE_BYTES);
        attr_set = true;
    }

    es_clear_kernel<<<(NTILES + 255) / 256, 256>>>();
    es_scan_kernel<<<NTILES, TPB, TILE_BYTES>>>(x, alpha, out);
}

// round 11
// speedup vs baseline: 1.5478x; 1.0970x over previous
#include <cuda_runtime.h>
#include <cuda_bf16.h>
#include <cstdint>

// ExponentialSmoothingLayer: s_0 = x_0; s_t = a*x_t + (1-a)*s_{t-1}, a = sigmoid(alpha[d])
// x: (B=16, T=4096, D=512) fp32 -> out same shape.
//
// v5: AGG-only truncated lookback, single launch.
//  - carry = sum_i Q^i * agg[tb-1-i] (+ Q^{tb-1} * incl0), truncated at Q^i < 1e-10
//    -> NO inclusive-status chain: wait target is only "predecessors scanned"
//  - epoch-encoded ready flags (status = epoch+1, epoch = ticket/NTILES)
//    -> no clear kernel, one launch per replay
//  - 4-chunk TMA (16 KB each): scan overlaps tail of the tile load
//  - window wait: warp 0 checks up to 32 ready flags per segment with one
//    coalesced read + __all_sync

#define B_  16
#define T_  4096
#define D_  512
#define L_  32
#define NTB (T_ / L_)            // 128 tiles per batch row
#define NTILES (B_ * NTB)        // 2048
#define TPB 512
#define TILE_BYTES (L_ * D_ * 4) // 65536
#define CHUNK_T 8                // timesteps per TMA chunk
#define NCHUNK (L_ / CHUNK_T)    // 4
#define CHUNK_BYTES (CHUNK_T * D_ * 4)  // 16384
#define THR 1e-10f

// -------- scratch (static device arrays; no runtime allocation) --------
__device__ float        g_agg [NTILES * D_];   // per-tile zero-state local last
__device__ float        g_incl0[B_ * D_];      // row-start true state (tile 0 only)
__device__ int          g_status[NTILES];      // ready flag: epoch+1 when published
__device__ unsigned int g_ticket;              // never reset; epoch = ticket/NTILES

// -------- PTX helpers --------
__device__ __forceinline__ int ld_acquire(const int* p) {
    int v; asm volatile("ld.acquire.gpu.s32 %0, [%1];" : "=r"(v) : "l"(p) : "memory"); return v;
}
__device__ __forceinline__ void st_release(int* p, int v) {
    asm volatile("st.release.gpu.s32 [%0], %1;" :: "l"(p), "r"(v) : "memory");
}
__device__ __forceinline__ unsigned smem_u32(const void* p) {
    unsigned a;
    asm("{ .reg .u64 t; cvta.to.shared.u64 t, %1; cvt.u32.u64 %0, t; }" : "=r"(a) : "l"(p));
    return a;
}
__device__ __forceinline__ void mbar_wait(unsigned mb) {  // parity 0, single-use
    unsigned done = 0;
    while (!done) {
        asm volatile(
            "{\n\t.reg .pred p;\n\t"
            "mbarrier.try_wait.parity.acquire.cta.shared::cta.b64 p, [%1], 0, 0x989680;\n\t"
            "selp.b32 %0, 1, 0, p;\n\t}"
            : "=r"(done) : "r"(mb) : "memory");
    }
}

__global__ void __launch_bounds__(TPB, 3)
es_scan_kernel(const float* __restrict__ x,
               const float* __restrict__ alpha,
               float* __restrict__ out) {
    extern __shared__ float tile[];                 // L_ * D_ floats (64 KB)
    __shared__ unsigned long long mbar[NCHUNK];
    __shared__ unsigned s_ticket;
    __shared__ int s_depth;

    const int tid = threadIdx.x;

    if (tid == 0) {
        const unsigned t0 = atomicAdd(&g_ticket, 1u);
        s_ticket = t0;
        s_depth  = 1;
        #pragma unroll
        for (int c = 0; c < NCHUNK; ++c)
            asm volatile("mbarrier.init.shared.b64 [%0], 1;"
                         :: "r"(smem_u32(&mbar[c])) : "memory");
        asm volatile("fence.proxy.async.shared::cta;" ::: "memory");

        // issue the 4 chunk loads immediately (before block-wide sync)
        const unsigned id0 = t0 & (NTILES - 1);
        const int b0 = (int)(id0 & (B_ - 1)), tb0 = (int)(id0 >> 4);
        const size_t base0 = ((size_t)b0 * T_ + (size_t)tb0 * L_) * (size_t)D_;
        #pragma unroll
        for (int c = 0; c < NCHUNK; ++c) {
            unsigned mb = smem_u32(&mbar[c]);
            asm volatile("mbarrier.arrive.expect_tx.shared.b64 _, [%0], %1;"
                         :: "r"(mb), "r"((unsigned)CHUNK_BYTES) : "memory");
            asm volatile("cp.async.bulk.shared::cta.global.mbarrier::complete_tx::bytes "
                         "[%0], [%1], %2, [%3];"
                         :: "r"(smem_u32(tile + (size_t)c * (CHUNK_T * D_))),
                            "l"(x + base0 + (size_t)c * (CHUNK_T * D_)),
                            "r"((unsigned)CHUNK_BYTES), "r"(mb) : "memory");
        }
    }
    __syncthreads();

    const unsigned tk    = s_ticket;
    const unsigned epoch = tk >> 11;                // tk / NTILES
    const unsigned id    = tk & (NTILES - 1);
    const int b   = (int)(id & (B_ - 1));
    const int tb  = (int)(id >> 4);
    const int lin = b * NTB + tb;
    const int ready = (int)(epoch + 1u);
    const size_t base = ((size_t)b * T_ + (size_t)tb * L_) * (size_t)D_;

    // per-channel coefficients (overlaps TMA)
    const float av = alpha[tid];
    const float a  = 1.0f / (1.0f + __expf(-av));
    const float q  = 1.0f - a;
    float Q = q;                                    // Q = q^32
    #pragma unroll
    for (int i = 0; i < 5; ++i) Q *= Q;

    // per-channel truncation depth: #terms with Q^i >= THR (>=1), block max
    {
        int nd = 1;
        float c = Q;
        while (c >= THR && nd < 96) { ++nd; c *= Q; }
        #pragma unroll
        for (int off = 16; off > 0; off >>= 1)
            nd = max(nd, __shfl_xor_sync(0xffffffffu, nd, off));
        if ((tid & 31) == 0) atomicMax(&s_depth, nd);
    }

    // ---- chunked scan: wait chunk, scan its 8 timesteps ----
    float s = 0.0f, x0 = 0.0f;
    #pragma unroll
    for (int c = 0; c < NCHUNK; ++c) {
        mbar_wait(smem_u32(&mbar[c]));
        #pragma unroll
        for (int t = c * CHUNK_T; t < (c + 1) * CHUNK_T; ++t) {
            float v = tile[t * D_ + tid];
            if (t == 0) x0 = v;
            s = fmaf(q, s, a * v);
            tile[t * D_ + tid] = s;
        }
    }
    const float last = s;

    // ---- publish (AGG for tb>0; exact row-start state for tb==0) ----
    if (tb == 0) g_incl0[b * D_ + tid] = fmaf(Q, x0, last);
    else         g_agg[(size_t)lin * D_ + tid] = last;
    __threadfence();
    __syncthreads();                                // also publishes s_depth
    if (tid == 0) st_release(&g_status[lin], ready);

    // ---- truncated AGG-only lookback ----
    float carry;
    if (tb == 0) {
        carry = x0;                                 // s_0 = x_0  <=>  S_in = x_0
    } else {
        const int dep = min(s_depth, tb);           // block-uniform
        carry = 0.0f;
        float coef = 1.0f;
        int done = 0;
        while (done < dep) {                        // usually one segment
            const int seg = min(32, dep - done);
            if (tid < 32) {                         // warp 0: wait seg ready flags
                const int i = done + tid;
                const int j = tb - 1 - i;
                const int* sp = &g_status[b * NTB + (j < 0 ? 0 : j)];
                for (;;) {
                    int st = (tid < seg) ? ld_acquire(sp) : ready;
                    if (__all_sync(0xffffffffu, st >= ready)) break;
                    __nanosleep(40);
                }
            }
            __syncthreads();
            #pragma unroll 1
            for (int ii = 0; ii < seg; ++ii) {
                const int j = tb - 1 - (done + ii);
                if (coef >= THR) {
                    const float val = (j == 0) ? g_incl0[b * D_ + tid]
                                               : g_agg[(size_t)(b * NTB + j) * D_ + tid];
                    carry = fmaf(coef, val, carry);
                }
                coef *= Q;
            }
            done += seg;
        }
    }

    // ---- fixup + coalesced store: s_{t0+t} = local_t + q^{t+1} * S_in ----
    float* op = out + base + tid;
    float c = q;
    #pragma unroll
    for (int t = 0; t < L_; ++t) {
        op[(size_t)t * D_] = fmaf(c, carry, tile[t * D_ + tid]);
        c *= q;
    }
}

extern "C" void kernel_launch(void* const* d_in, const int* in_sizes, int n_in,
                              void* d_out, int out_size) {
    const float* x     = (const float*)d_in[0];   // (16, 4096, 512) fp32
    const float* alpha = (const float*)d_in[1];   // (1, 1, 512) fp32
    float* out = (float*)d_out;
    (void)in_sizes; (void)n_in; (void)out_size;

    static bool attr_set = false;
    if (!attr_set) {
        cudaFuncSetAttribute(es_scan_kernel,
                             cudaFuncAttributeMaxDynamicSharedMemorySize,
                             TILE_BYTES);
        attr_set = true;
    }

    es_scan_kernel<<<NTILES, TPB, TILE_BYTES>>>(x, alpha, out);
}